// round 11
// baseline (speedup 1.0000x reference)
#include <cuda_runtime.h>

// SubglacialDrainageSystem: 64x64 grid, 5-point elliptic solve + closed-form
// sheet update. Single block (512 thr, 8 nodes/thread). Symmetric Jacobi
// scaling; fp32 Ghysels PIPELINED CG (one sync + one fused reduction per
// iteration, dot-product latency hidden under the SpMV); fp64 iterative
// refinement outer loop. Double-buffered smem w + partials.

#define NN      4096
#define NPAD    (NN + 128)
#define NT      512
#define PER     8

#define K_COND    0.01
#define SEC_PER_A 31556926.0
#define HR_       0.1
#define LR_       2.0
#define A_        5e-25

struct Smem {
    double cEd[NPAD];    // scaled E coupling (fp64)
    double cSd[NPAD];    // scaled S coupling (fp64)
    double Zs[NPAD];     // master solution (scaled), padded
    double Bt[NN];       // scaled rhs (fp64)
    double isd[NN];      // 1/sqrt(diag)
    double red[40];      // fp64 reduction scratch (16..31 zero)
    float2 red2[2][16];  // double-buffered fp32 warp partials (rho, delta)
    float  wfA[NPAD];    // w buffer A (padded, halo 0)
    float  wfB[NPAD];    // w buffer B (padded, halo 0)
    float  cSf[NPAD];    // fp32 copy of scaled S coupling
};

__device__ __forceinline__ double bred_d(double v, double* red, int tid) {
    #pragma unroll
    for (int o = 16; o > 0; o >>= 1) v += __shfl_down_sync(0xffffffffu, v, o);
    if ((tid & 31) == 0) red[tid >> 5] = v;
    __syncthreads();
    if (tid < 32) {
        double s = red[tid];
        #pragma unroll
        for (int o = 16; o > 0; o >>= 1) s += __shfl_down_sync(0xffffffffu, s, o);
        if (tid == 0) red[36] = s;
    }
    __syncthreads();
    return red[36];
}

__global__ void __launch_bounds__(NT, 1)
sgd_kernel(const float* __restrict__ base, const float* __restrict__ over,
           const float* __restrict__ melt, const float* __restrict__ sheet,
           const float* __restrict__ pot,  const float* __restrict__ svel,
           const float* __restrict__ llen, const int* __restrict__ lan,
           const int* __restrict__ inflow, float* __restrict__ out)
{
    extern __shared__ unsigned char smraw[];
    Smem& S = *reinterpret_cast<Smem*>(smraw);
    const int tid = threadIdx.x;
    const int lane = tid & 31;
    const int wid = tid >> 5;

    // ---- 1. zero padded arrays + scratch ----
    for (int k = tid; k < NPAD; k += NT) {
        S.cEd[k] = 0.0; S.cSd[k] = 0.0; S.Zs[k] = 0.0;
        S.wfA[k] = 0.f; S.wfB[k] = 0.f; S.cSf[k] = 0.f;
    }
    if (tid < 40) S.red[tid] = 0.0;
    __syncthreads();

    // ---- 2. raw per-link coefficients (fp64) ----
    #pragma unroll
    for (int nn = 0; nn < PER; nn++) {
        int i = tid + nn * NT;
        int col = i & 63, row = i >> 6;
        double pi = (double)pot[i], hi = (double)sheet[i];
        if (col < 63) {
            double len = (double)llen[row * 63 + col];
            double s = 0.5 * (hi + (double)sheet[i + 1]);
            double g = fabs(pi - (double)pot[i + 1]) / len;
            S.cEd[i + 64] = -K_COND * (s * sqrt(sqrt(s))) * len / sqrt(g);
        }
        if (row < 63) {
            double len = (double)llen[4032 + row * 64 + col];
            double s = 0.5 * (hi + (double)sheet[i + 64]);
            double g = fabs(pi - (double)pot[i + 64]) / len;
            S.cSd[i + 64] = -K_COND * (s * sqrt(sqrt(s))) * len / sqrt(g);
        }
    }
    __syncthreads();

    // ---- 3. diag, rhs (fold Dirichlet), scale factors, warm start, Bt ----
    #pragma unroll
    for (int nn = 0; nn < PER; nn++) {
        int i = tid + nn * NT;
        int col = i & 63, row = i >> 6;
        bool dir = (inflow[i] == 1);
        double cEi = S.cEd[i + 64];
        double cWi = S.cEd[i + 63];
        double cSi = S.cSd[i + 64];
        double cNi = S.cSd[i];
        double d, b;
        double dval = (double)base[i] - (double)over[i];
        if (dir) {
            d = 1.0; b = dval;
        } else {
            d = -(cEi + cWi + cSi + cNi);
            b = (double)melt[i];
            if (col < 63 && inflow[i + 1] == 1)
                b -= cEi * ((double)base[i + 1] - (double)over[i + 1]);
            if (col > 0 && inflow[i - 1] == 1)
                b -= cWi * ((double)base[i - 1] - (double)over[i - 1]);
            if (row < 63 && inflow[i + 64] == 1)
                b -= cSi * ((double)base[i + 64] - (double)over[i + 64]);
            if (row > 0 && inflow[i - 64] == 1)
                b -= cNi * ((double)base[i - 64] - (double)over[i - 64]);
        }
        double sq = sqrt(d);
        double is = 1.0 / sq;
        S.isd[i] = is;
        S.Bt[i] = b * is;
        S.Zs[i + 64] = dval * sq;     // warm start (scaled)
    }
    __syncthreads();

    // ---- 4. symmetric scaling + Dirichlet decoupling + fp32 S copy ----
    #pragma unroll
    for (int nn = 0; nn < PER; nn++) {
        int i = tid + nn * NT;
        int col = i & 63, row = i >> 6;
        bool dirI = (inflow[i] == 1);
        if (col < 63) {
            bool dirE = (inflow[i + 1] == 1);
            S.cEd[i + 64] = (dirI || dirE) ? 0.0
                          : S.cEd[i + 64] * S.isd[i] * S.isd[i + 1];
        }
        if (row < 63) {
            bool dirS = (inflow[i + 64] == 1);
            double v = (dirI || dirS) ? 0.0
                     : S.cSd[i + 64] * S.isd[i] * S.isd[i + 64];
            S.cSd[i + 64] = v;
        }
    }
    __syncthreads();
    #pragma unroll
    for (int nn = 0; nn < PER; nn++) {
        int i = tid + nn * NT;
        S.cSf[i + 64] = (float)S.cSd[i + 64];
    }
    __syncthreads();

    // ---- 5. E-coefficients in registers ----
    const int ib = tid * 8;
    const int ip = ib + 64;
    const float cW  = (float)S.cEd[ip - 1];
    const float cEa = (float)S.cEd[ip + 7];
    float cI[7];
    #pragma unroll
    for (int j = 0; j < 7; j++) cI[j] = (float)S.cEd[ip + j];

    double sb = 0.0;
    #pragma unroll
    for (int nn = 0; nn < PER; nn++) { double v = S.Bt[ib + nn]; sb += v * v; }
    const double rzb = bred_d(sb, S.red, tid);
    const double rz_target = rzb * 1e-14;

    const int own4 = tid * 2 + 16;                  // own nodes, float4 units
    float4* wA4 = reinterpret_cast<float4*>(S.wfA);
    float4* wB4 = reinterpret_cast<float4*>(S.wfB);
    const float4* cs4 = reinterpret_cast<const float4*>(S.cSf);

    // ---- 6. outer refinement passes ----
    for (int pass = 0; pass < 6; ++pass) {
        // fp64 residual of scaled system
        double rdv[PER];
        double rr = 0.0;
        #pragma unroll
        for (int nn = 0; nn < PER; nn++) {
            int i = ib + nn, j = ip + nn;
            double qd = S.Zs[j]
                      + S.cEd[j]      * S.Zs[j + 1]
                      + S.cEd[j - 1]  * S.Zs[j - 1]
                      + S.cSd[j]      * S.Zs[j + 64]
                      + S.cSd[j - 64] * S.Zs[j - 64];
            double rv = S.Bt[i] - qd;
            rdv[nn] = rv;
            rr += rv * rv;
        }
        rr = bred_d(rr, S.red, tid);
        if (!(rr > rz_target)) break;

        // ---- PIPECG init ----
        float r[PER], w[PER], p[PER], q[PER], z[PER], dx[PER];
        #pragma unroll
        for (int nn = 0; nn < PER; nn++) {
            r[nn] = (float)rdv[nn];
            p[nn] = 0.f; q[nn] = 0.f; z[nn] = 0.f; dx[nn] = 0.f;
        }
        // stage r into wfB
        wB4[own4 + 0] = make_float4(r[0], r[1], r[2], r[3]);
        wB4[own4 + 1] = make_float4(r[4], r[5], r[6], r[7]);
        __syncthreads();
        {   // w0 = A r0
            float rW = S.wfB[ip - 1], rE = S.wfB[ip + 8];
            float4 a0 = cs4[tid*2], a1 = cs4[tid*2 + 1];       // cN
            float4 b0 = cs4[own4],  b1 = cs4[own4 + 1];        // cS
            float4 n0 = wB4[own4 - 16], n1 = wB4[own4 - 15];
            float4 s0 = wB4[own4 + 16], s1 = wB4[own4 + 17];
            w[0] = r[0] + cW   *rW   + cI[0]*r[1] + a0.x*n0.x + b0.x*s0.x;
            w[1] = r[1] + cI[0]*r[0] + cI[1]*r[2] + a0.y*n0.y + b0.y*s0.y;
            w[2] = r[2] + cI[1]*r[1] + cI[2]*r[3] + a0.z*n0.z + b0.z*s0.z;
            w[3] = r[3] + cI[2]*r[2] + cI[3]*r[4] + a0.w*n0.w + b0.w*s0.w;
            w[4] = r[4] + cI[3]*r[3] + cI[4]*r[5] + a1.x*n1.x + b1.x*s1.x;
            w[5] = r[5] + cI[4]*r[4] + cI[5]*r[6] + a1.y*n1.y + b1.y*s1.y;
            w[6] = r[6] + cI[5]*r[5] + cI[6]*r[7] + a1.z*n1.z + b1.z*s1.z;
            w[7] = r[7] + cI[6]*r[6] + cEa  *rE   + a1.w*n1.w + b1.w*s1.w;
        }
        {   // partials (rho0, delta0) -> red2[0]; w0 -> wfA
            float pr = ((r[0]*r[0]+r[1]*r[1])+(r[2]*r[2]+r[3]*r[3]))
                     + ((r[4]*r[4]+r[5]*r[5])+(r[6]*r[6]+r[7]*r[7]));
            float pd = ((w[0]*r[0]+w[1]*r[1])+(w[2]*r[2]+w[3]*r[3]))
                     + ((w[4]*r[4]+w[5]*r[5])+(w[6]*r[6]+w[7]*r[7]));
            #pragma unroll
            for (int o = 16; o > 0; o >>= 1) {
                pr += __shfl_down_sync(0xffffffffu, pr, o);
                pd += __shfl_down_sync(0xffffffffu, pd, o);
            }
            if (lane == 0) S.red2[0][wid] = make_float2(pr, pd);
            wA4[own4 + 0] = make_float4(w[0], w[1], w[2], w[3]);
            wA4[own4 + 1] = make_float4(w[4], w[5], w[6], w[7]);
        }
        __syncthreads();

        const float tolp = fmaxf((float)rz_target, (float)rr * 1e-10f);
        const int cap = (pass == 0) ? 1200 : 600;
        float rho_old = 1.f, alpha_old = 1.f;
        float rzchk = (float)rr;

        for (int it = 0; it < cap; ++it) {
            const int par = it & 1;
            // stage-2 reduce (overlaps with SpMV below via ILP)
            float2 v = S.red2[par][lane & 15];
            float rho = v.x, del = v.y;
            #pragma unroll
            for (int o = 8; o > 0; o >>= 1) {
                rho += __shfl_xor_sync(0xffffffffu, rho, o);
                del += __shfl_xor_sync(0xffffffffu, del, o);
            }
            // SpMV n = A w (reads regs for own E/W, smem buf[par] for halo/N/S)
            const float*  wb  = par ? S.wfB : S.wfA;
            const float4* wb4 = par ? wB4 : wA4;
            float wW = wb[ip - 1], wE = wb[ip + 8];
            float4 a0 = cs4[tid*2], a1 = cs4[tid*2 + 1];
            float4 b0 = cs4[own4],  b1 = cs4[own4 + 1];
            float4 n0 = wb4[own4 - 16], n1 = wb4[own4 - 15];
            float4 s0 = wb4[own4 + 16], s1 = wb4[own4 + 17];
            float n_[PER];
            n_[0] = w[0] + cW   *wW   + cI[0]*w[1] + a0.x*n0.x + b0.x*s0.x;
            n_[1] = w[1] + cI[0]*w[0] + cI[1]*w[2] + a0.y*n0.y + b0.y*s0.y;
            n_[2] = w[2] + cI[1]*w[1] + cI[2]*w[3] + a0.z*n0.z + b0.z*s0.z;
            n_[3] = w[3] + cI[2]*w[2] + cI[3]*w[4] + a0.w*n0.w + b0.w*s0.w;
            n_[4] = w[4] + cI[3]*w[3] + cI[4]*w[5] + a1.x*n1.x + b1.x*s1.x;
            n_[5] = w[5] + cI[4]*w[4] + cI[5]*w[6] + a1.y*n1.y + b1.y*s1.y;
            n_[6] = w[6] + cI[5]*w[5] + cI[6]*w[7] + a1.z*n1.z + b1.z*s1.z;
            n_[7] = w[7] + cI[6]*w[6] + cEa  *wE   + a1.w*n1.w + b1.w*s1.w;

            if (!(rho > tolp)) break;                 // also catches NaN
            if ((it & 255) == 255) {                  // stagnation guard
                if (rho > 0.9f * rzchk) break;
                rzchk = rho;
            }
            float beta  = (it == 0) ? 0.f : __fdividef(rho, rho_old);
            float denom = del - beta * __fdividef(rho, alpha_old);
            if (!(denom > 0.f)) break;
            float alpha = __fdividef(rho, denom);
            rho_old = rho; alpha_old = alpha;

            #pragma unroll
            for (int nn = 0; nn < PER; nn++) {
                z[nn] = n_[nn] + beta * z[nn];
                q[nn] = w[nn] + beta * q[nn];
                p[nn] = r[nn] + beta * p[nn];
                dx[nn] += alpha * p[nn];
                r[nn]  -= alpha * q[nn];
                w[nn]  -= alpha * z[nn];
            }
            // partials for next iteration
            float pr = ((r[0]*r[0]+r[1]*r[1])+(r[2]*r[2]+r[3]*r[3]))
                     + ((r[4]*r[4]+r[5]*r[5])+(r[6]*r[6]+r[7]*r[7]));
            float pd = ((w[0]*r[0]+w[1]*r[1])+(w[2]*r[2]+w[3]*r[3]))
                     + ((w[4]*r[4]+w[5]*r[5])+(w[6]*r[6]+w[7]*r[7]));
            #pragma unroll
            for (int o = 16; o > 0; o >>= 1) {
                pr += __shfl_down_sync(0xffffffffu, pr, o);
                pd += __shfl_down_sync(0xffffffffu, pd, o);
            }
            if (lane == 0) S.red2[1 - par][wid] = make_float2(pr, pd);
            float4* wo4 = par ? wA4 : wB4;
            wo4[own4 + 0] = make_float4(w[0], w[1], w[2], w[3]);
            wo4[own4 + 1] = make_float4(w[4], w[5], w[6], w[7]);
            __syncthreads();
        }

        // accumulate correction into fp64 master
        __syncthreads();
        #pragma unroll
        for (int nn = 0; nn < PER; nn++) S.Zs[ip + nn] += (double)dx[nn];
        __syncthreads();
    }

    // ---- 7. outputs: potential + closed-form sheet thickness ----
    const double dtf = 3600.0;
    #pragma unroll
    for (int nn = 0; nn < PER; nn++) {
        int i = ib + nn;
        double x = S.Zs[ip + nn] * S.isd[i];
        out[i] = (float)x;
        double P = (double)base[i] - x;
        const int* la = lan + 4 * i;
        double ssum = 0.0; int cnt = 0;
        #pragma unroll
        for (int k = 0; k < 4; k++) {
            int l = la[k];
            if (l >= 0) { ssum += (double)svel[l]; cnt++; }
        }
        double sliding = fabs(ssum / SEC_PER_A) / (double)(cnt > 0 ? cnt : 1);
        double nh = ((double)sheet[i] + dtf * sliding * HR_ / LR_)
                  / (1.0 + dtf * (sliding / LR_ + A_ * P * P * P));
        out[NN + i] = (float)nh;
    }
}

extern "C" void kernel_launch(void* const* d_in, const int* in_sizes, int n_in,
                              void* d_out, int out_size)
{
    const float* base  = (const float*)d_in[0];
    const float* over  = (const float*)d_in[1];
    const float* melt  = (const float*)d_in[2];
    const float* sheet = (const float*)d_in[3];
    const float* pot   = (const float*)d_in[4];
    const float* svel  = (const float*)d_in[5];
    const float* llen  = (const float*)d_in[6];
    const int*   lan   = (const int*)d_in[9];
    const int*   infl  = (const int*)d_in[10];
    float* out = (float*)d_out;

    int smem = (int)sizeof(Smem);
    cudaFuncSetAttribute(sgd_kernel, cudaFuncAttributeMaxDynamicSharedMemorySize, smem);
    sgd_kernel<<<1, NT, smem>>>(base, over, melt, sheet, pot, svel, llen, lan, infl, out);
}

// round 12
// speedup vs baseline: 1.7486x; 1.7486x over previous
#include <cuda_runtime.h>

// SubglacialDrainageSystem: 64x64 grid, 5-point elliptic solve + closed-form
// sheet update. Single block (512 thr, 8 nodes/thread). Symmetric Jacobi
// scaling; fp32 Chronopoulos-Gear PCG (ONE fused 3-dot reduction / iter)
// with degree-3 CHEBYSHEV polynomial preconditioner (3 dot-free SpMVs);
// fp64 iterative-refinement outer loop. R9-proven numerics core.

#define NN      4096
#define NPAD    (NN + 128)
#define NT      512
#define PER     8

#define K_COND    0.01
#define SEC_PER_A 31556926.0
#define HR_       0.1
#define LR_       2.0
#define A_        5e-25

struct Smem {
    double cEd[NPAD];    // scaled E coupling (fp64)
    double cSd[NPAD];    // scaled S coupling (fp64)
    double Zs[NPAD];     // master solution (scaled), padded
    double Bt[NN];       // scaled rhs (fp64)
    double isd[NN];      // 1/sqrt(diag)
    double red[40];      // fp64 reduction scratch (16..31 zero)
    float4 red4[16];     // fp32 fused 3-dot warp partials
    float  wfA[NPAD];    // staging buffer A (padded, halo 0)
    float  wfB[NPAD];    // staging buffer B (padded, halo 0)
    float  cSf[NPAD];    // fp32 copy of scaled S coupling
};

__device__ __forceinline__ double bred_d(double v, double* red, int tid) {
    #pragma unroll
    for (int o = 16; o > 0; o >>= 1) v += __shfl_down_sync(0xffffffffu, v, o);
    if ((tid & 31) == 0) red[tid >> 5] = v;
    __syncthreads();
    if (tid < 32) {
        double s = red[tid];
        #pragma unroll
        for (int o = 16; o > 0; o >>= 1) s += __shfl_down_sync(0xffffffffu, s, o);
        if (tid == 0) red[36] = s;
    }
    __syncthreads();
    return red[36];
}

__device__ __forceinline__ double bred_dmax(double v, double* red, int tid) {
    #pragma unroll
    for (int o = 16; o > 0; o >>= 1) v = fmax(v, __shfl_down_sync(0xffffffffu, v, o));
    if ((tid & 31) == 0) red[tid >> 5] = v;
    __syncthreads();
    if (tid < 32) {
        double s = red[tid];              // slots 16..31 zero; values >=1 so ok
        #pragma unroll
        for (int o = 16; o > 0; o >>= 1) s = fmax(s, __shfl_down_sync(0xffffffffu, s, o));
        if (tid == 0) red[36] = s;
    }
    __syncthreads();
    return red[36];
}

// Fused 3-component block reduction, ONE sync; every lane returns all sums.
__device__ __forceinline__ float3 bred3f(float a, float b, float c,
                                         float4* red4, int tid) {
    #pragma unroll
    for (int o = 16; o > 0; o >>= 1) {
        a += __shfl_down_sync(0xffffffffu, a, o);
        b += __shfl_down_sync(0xffffffffu, b, o);
        c += __shfl_down_sync(0xffffffffu, c, o);
    }
    if ((tid & 31) == 0) red4[tid >> 5] = make_float4(a, b, c, 0.f);
    __syncthreads();
    float4 v = red4[tid & 15];    // two half-warps hold identical 16 partials
    float x = v.x, y = v.y, z = v.z;
    #pragma unroll
    for (int o = 8; o > 0; o >>= 1) {
        x += __shfl_xor_sync(0xffffffffu, x, o);
        y += __shfl_xor_sync(0xffffffffu, y, o);
        z += __shfl_xor_sync(0xffffffffu, z, o);
    }
    return make_float3(x, y, z);
}

__global__ void __launch_bounds__(NT, 1)
sgd_kernel(const float* __restrict__ base, const float* __restrict__ over,
           const float* __restrict__ melt, const float* __restrict__ sheet,
           const float* __restrict__ pot,  const float* __restrict__ svel,
           const float* __restrict__ llen, const int* __restrict__ lan,
           const int* __restrict__ inflow, float* __restrict__ out)
{
    extern __shared__ unsigned char smraw[];
    Smem& S = *reinterpret_cast<Smem*>(smraw);
    const int tid = threadIdx.x;

    // ---- 1. zero padded arrays + scratch ----
    for (int k = tid; k < NPAD; k += NT) {
        S.cEd[k] = 0.0; S.cSd[k] = 0.0; S.Zs[k] = 0.0;
        S.wfA[k] = 0.f; S.wfB[k] = 0.f; S.cSf[k] = 0.f;
    }
    if (tid < 40) S.red[tid] = 0.0;
    __syncthreads();

    // ---- 2. raw per-link coefficients (fp64) ----
    #pragma unroll
    for (int nn = 0; nn < PER; nn++) {
        int i = tid + nn * NT;
        int col = i & 63, row = i >> 6;
        double pi = (double)pot[i], hi = (double)sheet[i];
        if (col < 63) {
            double len = (double)llen[row * 63 + col];
            double s = 0.5 * (hi + (double)sheet[i + 1]);
            double g = fabs(pi - (double)pot[i + 1]) / len;
            S.cEd[i + 64] = -K_COND * (s * sqrt(sqrt(s))) * len / sqrt(g);
        }
        if (row < 63) {
            double len = (double)llen[4032 + row * 64 + col];
            double s = 0.5 * (hi + (double)sheet[i + 64]);
            double g = fabs(pi - (double)pot[i + 64]) / len;
            S.cSd[i + 64] = -K_COND * (s * sqrt(sqrt(s))) * len / sqrt(g);
        }
    }
    __syncthreads();

    // ---- 3. diag, rhs (fold Dirichlet), scale factors, warm start, Bt ----
    #pragma unroll
    for (int nn = 0; nn < PER; nn++) {
        int i = tid + nn * NT;
        int col = i & 63, row = i >> 6;
        bool dir = (inflow[i] == 1);
        double cEi = S.cEd[i + 64];
        double cWi = S.cEd[i + 63];
        double cSi = S.cSd[i + 64];
        double cNi = S.cSd[i];
        double d, b;
        double dval = (double)base[i] - (double)over[i];
        if (dir) {
            d = 1.0; b = dval;
        } else {
            d = -(cEi + cWi + cSi + cNi);
            b = (double)melt[i];
            if (col < 63 && inflow[i + 1] == 1)
                b -= cEi * ((double)base[i + 1] - (double)over[i + 1]);
            if (col > 0 && inflow[i - 1] == 1)
                b -= cWi * ((double)base[i - 1] - (double)over[i - 1]);
            if (row < 63 && inflow[i + 64] == 1)
                b -= cSi * ((double)base[i + 64] - (double)over[i + 64]);
            if (row > 0 && inflow[i - 64] == 1)
                b -= cNi * ((double)base[i - 64] - (double)over[i - 64]);
        }
        double sq = sqrt(d);
        double is = 1.0 / sq;
        S.isd[i] = is;
        S.Bt[i] = b * is;
        S.Zs[i + 64] = dval * sq;     // warm start (scaled)
    }
    __syncthreads();

    // ---- 4. symmetric scaling + Dirichlet decoupling ----
    #pragma unroll
    for (int nn = 0; nn < PER; nn++) {
        int i = tid + nn * NT;
        int col = i & 63, row = i >> 6;
        bool dirI = (inflow[i] == 1);
        if (col < 63) {
            bool dirE = (inflow[i + 1] == 1);
            S.cEd[i + 64] = (dirI || dirE) ? 0.0
                          : S.cEd[i + 64] * S.isd[i] * S.isd[i + 1];
        }
        if (row < 63) {
            bool dirS = (inflow[i + 64] == 1);
            S.cSd[i + 64] = (dirI || dirS) ? 0.0
                          : S.cSd[i + 64] * S.isd[i] * S.isd[i + 64];
        }
    }
    __syncthreads();
    // fp32 S-coupling copy + Gershgorin row sums (scaled couplings are <= 0)
    double gmax = 1.0;
    #pragma unroll
    for (int nn = 0; nn < PER; nn++) {
        int i = tid + nn * NT;
        S.cSf[i + 64] = (float)S.cSd[i + 64];
        double srow = 1.0 - (S.cEd[i + 64] + S.cEd[i + 63]
                           + S.cSd[i + 64] + S.cSd[i]);
        gmax = fmax(gmax, srow);
    }
    __syncthreads();
    const double lmax = bred_dmax(gmax, S.red, tid) * 1.0005;

    // Chebyshev interval [a, b] and recurrence constants (fp32, uniform)
    const float bF = (float)lmax;
    const float aF = bF * 0.04f;                 // b/25
    const float thetaF = 0.5f * (bF + aF);
    const float deltaF = 0.5f * (bF - aF);
    const float inv_th = 1.0f / thetaF;
    const float sigma1 = thetaF / deltaF;
    const float rho0C  = 1.0f / sigma1;
    const float two_sg = 2.0f * sigma1;
    const float two_id = 2.0f / deltaF;

    // ---- 5. E-coefficients in registers ----
    const int ib = tid * 8;
    const int ip = ib + 64;
    const float cW  = (float)S.cEd[ip - 1];
    const float cEa = (float)S.cEd[ip + 7];
    float cI[7];
    #pragma unroll
    for (int j = 0; j < 7; j++) cI[j] = (float)S.cEd[ip + j];

    double sb = 0.0;
    #pragma unroll
    for (int nn = 0; nn < PER; nn++) { double v = S.Bt[ib + nn]; sb += v * v; }
    const double rzb = bred_d(sb, S.red, tid);
    const double rz_target = rzb * 1e-16;

    const int own4 = tid * 2 + 16;
    float4* wA4 = reinterpret_cast<float4*>(S.wfA);
    float4* wB4 = reinterpret_cast<float4*>(S.wfB);
    const float4* cs4 = reinterpret_cast<const float4*>(S.cSf);

    // SpMV: t = A~ v, own values in regs, halo/N/S rows from buffer
    auto spmv = [&](const float* wb, const float4* wb4,
                    const float v[PER], float t[PER]) {
        float vW = wb[ip - 1], vE = wb[ip + 8];
        float4 a0 = cs4[tid * 2], a1 = cs4[tid * 2 + 1];   // cN
        float4 b0 = cs4[own4],    b1 = cs4[own4 + 1];      // cS
        float4 n0 = wb4[own4 - 16], n1 = wb4[own4 - 15];
        float4 s0 = wb4[own4 + 16], s1 = wb4[own4 + 17];
        t[0] = v[0] + cW   *vW   + cI[0]*v[1] + a0.x*n0.x + b0.x*s0.x;
        t[1] = v[1] + cI[0]*v[0] + cI[1]*v[2] + a0.y*n0.y + b0.y*s0.y;
        t[2] = v[2] + cI[1]*v[1] + cI[2]*v[3] + a0.z*n0.z + b0.z*s0.z;
        t[3] = v[3] + cI[2]*v[2] + cI[3]*v[4] + a0.w*n0.w + b0.w*s0.w;
        t[4] = v[4] + cI[3]*v[3] + cI[4]*v[5] + a1.x*n1.x + b1.x*s1.x;
        t[5] = v[5] + cI[4]*v[4] + cI[5]*v[6] + a1.y*n1.y + b1.y*s1.y;
        t[6] = v[6] + cI[5]*v[5] + cI[6]*v[7] + a1.z*n1.z + b1.z*s1.z;
        t[7] = v[7] + cI[6]*v[6] + cEa  *vE   + a1.w*n1.w + b1.w*s1.w;
    };
    auto store8 = [&](float4* dst4, const float v[PER]) {
        dst4[own4 + 0] = make_float4(v[0], v[1], v[2], v[3]);
        dst4[own4 + 1] = make_float4(v[4], v[5], v[6], v[7]);
    };

    // ---- 6. outer refinement passes ----
    for (int pass = 0; pass < 6; ++pass) {
        // fp64 residual of scaled system
        double rdv[PER];
        double rr64 = 0.0;
        #pragma unroll
        for (int nn = 0; nn < PER; nn++) {
            int i = ib + nn, j = ip + nn;
            double qd = S.Zs[j]
                      + S.cEd[j]      * S.Zs[j + 1]
                      + S.cEd[j - 1]  * S.Zs[j - 1]
                      + S.cSd[j]      * S.Zs[j + 64]
                      + S.cSd[j - 64] * S.Zs[j - 64];
            double rv = S.Bt[i] - qd;
            rdv[nn] = rv;
            rr64 += rv * rv;
        }
        rr64 = bred_d(rr64, S.red, tid);
        if (!(rr64 > rz_target)) break;

        // ---- fp32 Chebyshev-preconditioned Chronopoulos-Gear PCG ----
        float r[PER], p[PER], q[PER], dx[PER];
        #pragma unroll
        for (int nn = 0; nn < PER; nn++) {
            r[nn] = (float)rdv[nn];
            p[nn] = 0.f; q[nn] = 0.f; dx[nn] = 0.f;
        }
        const float tolp = fmaxf((float)rz_target, (float)rr64 * 1e-11f);
        const int cap = (pass == 0) ? 500 : 300;
        float rho_old = 1.f, alpha_old = 1.f;
        float rrchk = (float)rr64;

        for (int it = 0; it < cap; ++it) {
            // --- z = P3(A) r (Chebyshev, dot-free) ---
            float d_[PER], z[PER], rin[PER], t[PER];
            #pragma unroll
            for (int nn = 0; nn < PER; nn++) {
                d_[nn] = r[nn] * inv_th; z[nn] = d_[nn]; rin[nn] = r[nn];
            }
            store8(wA4, d_);                       // d0 -> A
            float rhoC = rho0C;
            // step 1: read A, write B
            __syncthreads();
            spmv(S.wfA, wA4, d_, t);
            {
                float rhoN = __fdividef(1.f, two_sg - rhoC);
                float c1 = rhoN * rhoC, c2 = two_id * rhoN;
                #pragma unroll
                for (int nn = 0; nn < PER; nn++) {
                    rin[nn] -= t[nn];
                    d_[nn] = c1 * d_[nn] + c2 * rin[nn];
                    z[nn] += d_[nn];
                }
                rhoC = rhoN;
            }
            store8(wB4, d_);
            // step 2: read B, write A
            __syncthreads();
            spmv(S.wfB, wB4, d_, t);
            {
                float rhoN = __fdividef(1.f, two_sg - rhoC);
                float c1 = rhoN * rhoC, c2 = two_id * rhoN;
                #pragma unroll
                for (int nn = 0; nn < PER; nn++) {
                    rin[nn] -= t[nn];
                    d_[nn] = c1 * d_[nn] + c2 * rin[nn];
                    z[nn] += d_[nn];
                }
                rhoC = rhoN;
            }
            store8(wA4, d_);
            // step 3: read A, no store of d3
            __syncthreads();
            spmv(S.wfA, wA4, d_, t);
            {
                float rhoN = __fdividef(1.f, two_sg - rhoC);
                float c1 = rhoN * rhoC, c2 = two_id * rhoN;
                #pragma unroll
                for (int nn = 0; nn < PER; nn++) {
                    rin[nn] -= t[nn];
                    d_[nn] = c1 * d_[nn] + c2 * rin[nn];
                    z[nn] += d_[nn];
                }
            }
            // --- w = A z ---
            __syncthreads();                       // cover step-3 reads of A
            store8(wA4, z);
            __syncthreads();
            float w[PER];
            spmv(S.wfA, wA4, z, w);

            // --- fused dots: rho=(r,z), mu=(z,w), rr=(r,r) ---
            float pr = 0.f, pm = 0.f, prr = 0.f;
            #pragma unroll
            for (int nn = 0; nn < PER; nn++) {
                pr += r[nn] * z[nn];
                pm += z[nn] * w[nn];
                prr += r[nn] * r[nn];
            }
            float3 dsum = bred3f(pr, pm, prr, S.red4, tid);   // 1 sync
            float rho = dsum.x, mu = dsum.y, rr = dsum.z;

            if (!(rr > tolp)) break;               // catches NaN too
            if ((it & 63) == 63) {                 // stagnation guard
                if (rr > 0.9f * rrchk) break;
                rrchk = rr;
            }
            if (!(rho > 0.f) || !(mu > 0.f)) break;

            float beta  = (it == 0) ? 0.f : __fdividef(rho, rho_old);
            float denom = mu - beta * __fdividef(rho, alpha_old);
            if (!(denom > 0.f)) break;
            float alpha = __fdividef(rho, denom);
            rho_old = rho; alpha_old = alpha;

            #pragma unroll
            for (int nn = 0; nn < PER; nn++) {
                p[nn] = z[nn] + beta * p[nn];
                q[nn] = w[nn] + beta * q[nn];
                dx[nn] += alpha * p[nn];
                r[nn]  -= alpha * q[nn];
            }
            // next iter's d0 store to A is WAR-safe: bred3f sync separates
        }

        // accumulate correction into fp64 master
        __syncthreads();
        #pragma unroll
        for (int nn = 0; nn < PER; nn++) S.Zs[ip + nn] += (double)dx[nn];
        __syncthreads();
    }

    // ---- 7. outputs: potential + closed-form sheet thickness ----
    const double dtf = 3600.0;
    #pragma unroll
    for (int nn = 0; nn < PER; nn++) {
        int i = ib + nn;
        double x = S.Zs[ip + nn] * S.isd[i];
        out[i] = (float)x;
        double P = (double)base[i] - x;
        const int* la = lan + 4 * i;
        double ssum = 0.0; int cnt = 0;
        #pragma unroll
        for (int k = 0; k < 4; k++) {
            int l = la[k];
            if (l >= 0) { ssum += (double)svel[l]; cnt++; }
        }
        double sliding = fabs(ssum / SEC_PER_A) / (double)(cnt > 0 ? cnt : 1);
        double nh = ((double)sheet[i] + dtf * sliding * HR_ / LR_)
                  / (1.0 + dtf * (sliding / LR_ + A_ * P * P * P));
        out[NN + i] = (float)nh;
    }
}

extern "C" void kernel_launch(void* const* d_in, const int* in_sizes, int n_in,
                              void* d_out, int out_size)
{
    const float* base  = (const float*)d_in[0];
    const float* over  = (const float*)d_in[1];
    const float* melt  = (const float*)d_in[2];
    const float* sheet = (const float*)d_in[3];
    const float* pot   = (const float*)d_in[4];
    const float* svel  = (const float*)d_in[5];
    const float* llen  = (const float*)d_in[6];
    const int*   lan   = (const int*)d_in[9];
    const int*   infl  = (const int*)d_in[10];
    float* out = (float*)d_out;

    int smem = (int)sizeof(Smem);
    cudaFuncSetAttribute(sgd_kernel, cudaFuncAttributeMaxDynamicSharedMemorySize, smem);
    sgd_kernel<<<1, NT, smem>>>(base, over, melt, sheet, pot, svel, llen, lan, infl, out);
}

// round 14
// speedup vs baseline: 2.2802x; 1.3040x over previous
#include <cuda_runtime.h>

// SubglacialDrainageSystem: 64x64 grid, 5-point elliptic solve + closed-form
// sheet update. Single block, 512 thr. WARP-BAND layout: warp w owns rows
// 4w..4w+3, lane l owns cols 2l,2l+1 -> N/S register-local, E/W via shfl,
// only band-boundary rows cross warps (double-buffered smem ghosts, 1 sync
// per SpMV). fp32 Chronopoulos-Gear PCG + degree-8 Chebyshev preconditioner
// (dot-free); ONE fused 3-dot reduction per outer iter; fp64 refinement.

#define NN      4096
#define NPAD    (NN + 128)
#define NT      512
#define PER     8
#define CHEB_D  8

#define K_COND    0.01
#define SEC_PER_A 31556926.0
#define HR_       0.1
#define LR_       2.0
#define A_        5e-25

struct Smem {
    double cEd[NPAD];     // scaled E coupling (fp64), cEd[i+64] couples i,i+1
    double cSd[NPAD];     // scaled S coupling (fp64), cSd[i+64] couples i,i+64
    double Zs[NPAD];      // master solution (scaled), padded, halo 0
    double Bt[NN];        // scaled rhs (fp64)
    double isd[NN];       // 1/sqrt(diag)
    double red[40];       // fp64 reduction scratch (16..31 zero)
    float4 red4[16];      // fp32 fused 3-dot warp partials
    float  gTop[2][18][64];  // [buf][warp+1][col] row 4w values; 0,17 = zero
    float  gBot[2][18][64];  // [buf][warp+1][col] row 4w+3 values
};

__device__ __forceinline__ double bred_d(double v, double* red, int tid) {
    #pragma unroll
    for (int o = 16; o > 0; o >>= 1) v += __shfl_down_sync(0xffffffffu, v, o);
    if ((tid & 31) == 0) red[tid >> 5] = v;
    __syncthreads();
    if (tid < 32) {
        double s = red[tid];
        #pragma unroll
        for (int o = 16; o > 0; o >>= 1) s += __shfl_down_sync(0xffffffffu, s, o);
        if (tid == 0) red[36] = s;
    }
    __syncthreads();
    return red[36];
}

__device__ __forceinline__ double bred_dmax(double v, double* red, int tid) {
    #pragma unroll
    for (int o = 16; o > 0; o >>= 1) v = fmax(v, __shfl_down_sync(0xffffffffu, v, o));
    if ((tid & 31) == 0) red[tid >> 5] = v;
    __syncthreads();
    if (tid < 32) {
        double s = red[tid];
        #pragma unroll
        for (int o = 16; o > 0; o >>= 1) s = fmax(s, __shfl_down_sync(0xffffffffu, s, o));
        if (tid == 0) red[36] = s;
    }
    __syncthreads();
    return red[36];
}

// Fused 3-component block reduction, ONE sync; every lane returns all sums.
__device__ __forceinline__ float3 bred3f(float a, float b, float c,
                                         float4* red4, int tid) {
    #pragma unroll
    for (int o = 16; o > 0; o >>= 1) {
        a += __shfl_down_sync(0xffffffffu, a, o);
        b += __shfl_down_sync(0xffffffffu, b, o);
        c += __shfl_down_sync(0xffffffffu, c, o);
    }
    if ((tid & 31) == 0) red4[tid >> 5] = make_float4(a, b, c, 0.f);
    __syncthreads();
    float4 v = red4[tid & 15];
    float x = v.x, y = v.y, z = v.z;
    #pragma unroll
    for (int o = 8; o > 0; o >>= 1) {
        x += __shfl_xor_sync(0xffffffffu, x, o);
        y += __shfl_xor_sync(0xffffffffu, y, o);
        z += __shfl_xor_sync(0xffffffffu, z, o);
    }
    return make_float3(x, y, z);
}

__global__ void __launch_bounds__(NT, 1)
sgd_kernel(const float* __restrict__ base, const float* __restrict__ over,
           const float* __restrict__ melt, const float* __restrict__ sheet,
           const float* __restrict__ pot,  const float* __restrict__ svel,
           const float* __restrict__ llen, const int* __restrict__ lan,
           const int* __restrict__ inflow, float* __restrict__ out)
{
    extern __shared__ unsigned char smraw[];
    Smem& S = *reinterpret_cast<Smem*>(smraw);
    const int tid = threadIdx.x;
    const int wrp = tid >> 5;
    const int ln  = tid & 31;

    // ---- 1. zero padded arrays + scratch + ghost buffers ----
    for (int k = tid; k < NPAD; k += NT) { S.cEd[k] = 0.0; S.cSd[k] = 0.0; S.Zs[k] = 0.0; }
    {
        float* g = &S.gTop[0][0][0];
        for (int k = tid; k < 2 * 2 * 18 * 64; k += NT) g[k] = 0.f;
    }
    if (tid < 40) S.red[tid] = 0.0;
    __syncthreads();

    // ---- 2. raw per-link coefficients (fp64), strided mapping ----
    #pragma unroll
    for (int nn = 0; nn < PER; nn++) {
        int i = tid + nn * NT;
        int col = i & 63, row = i >> 6;
        double pi = (double)pot[i], hi = (double)sheet[i];
        if (col < 63) {
            double len = (double)llen[row * 63 + col];
            double s = 0.5 * (hi + (double)sheet[i + 1]);
            double g = fabs(pi - (double)pot[i + 1]) / len;
            S.cEd[i + 64] = -K_COND * (s * sqrt(sqrt(s))) * len / sqrt(g);
        }
        if (row < 63) {
            double len = (double)llen[4032 + row * 64 + col];
            double s = 0.5 * (hi + (double)sheet[i + 64]);
            double g = fabs(pi - (double)pot[i + 64]) / len;
            S.cSd[i + 64] = -K_COND * (s * sqrt(sqrt(s))) * len / sqrt(g);
        }
    }
    __syncthreads();

    // ---- 3. diag, rhs (fold Dirichlet), scale factors, warm start ----
    #pragma unroll
    for (int nn = 0; nn < PER; nn++) {
        int i = tid + nn * NT;
        int col = i & 63, row = i >> 6;
        bool dir = (inflow[i] == 1);
        double cEi = S.cEd[i + 64];
        double cWi = S.cEd[i + 63];
        double cSi = S.cSd[i + 64];
        double cNi = S.cSd[i];
        double d, b;
        double dval = (double)base[i] - (double)over[i];
        if (dir) {
            d = 1.0; b = dval;
        } else {
            d = -(cEi + cWi + cSi + cNi);
            b = (double)melt[i];
            if (col < 63 && inflow[i + 1] == 1)
                b -= cEi * ((double)base[i + 1] - (double)over[i + 1]);
            if (col > 0 && inflow[i - 1] == 1)
                b -= cWi * ((double)base[i - 1] - (double)over[i - 1]);
            if (row < 63 && inflow[i + 64] == 1)
                b -= cSi * ((double)base[i + 64] - (double)over[i + 64]);
            if (row > 0 && inflow[i - 64] == 1)
                b -= cNi * ((double)base[i - 64] - (double)over[i - 64]);
        }
        double sq = sqrt(d);
        double is = 1.0 / sq;
        S.isd[i] = is;
        S.Bt[i] = b * is;
        S.Zs[i + 64] = dval * sq;
    }
    __syncthreads();

    // ---- 4. symmetric scaling + Dirichlet decoupling + Gershgorin ----
    #pragma unroll
    for (int nn = 0; nn < PER; nn++) {
        int i = tid + nn * NT;
        int col = i & 63, row = i >> 6;
        bool dirI = (inflow[i] == 1);
        if (col < 63) {
            bool dirE = (inflow[i + 1] == 1);
            S.cEd[i + 64] = (dirI || dirE) ? 0.0
                          : S.cEd[i + 64] * S.isd[i] * S.isd[i + 1];
        }
        if (row < 63) {
            bool dirS = (inflow[i + 64] == 1);
            S.cSd[i + 64] = (dirI || dirS) ? 0.0
                          : S.cSd[i + 64] * S.isd[i] * S.isd[i + 64];
        }
    }
    __syncthreads();
    double gmax = 1.0;
    #pragma unroll
    for (int nn = 0; nn < PER; nn++) {
        int i = tid + nn * NT;
        double srow = 1.0 - (S.cEd[i + 64] + S.cEd[i + 63]
                           + S.cSd[i + 64] + S.cSd[i]);
        gmax = fmax(gmax, srow);
    }
    const double lmax = bred_dmax(gmax, S.red, tid) * 1.0005;

    // Chebyshev constants (interval [b/25, b], validated in R12)
    const float bF = (float)lmax;
    const float aF = bF * 0.04f;
    const float thetaF = 0.5f * (bF + aF);
    const float deltaF = 0.5f * (bF - aF);
    const float inv_th = 1.0f / thetaF;
    const float sigma1 = thetaF / deltaF;
    const float rho0C  = 1.0f / sigma1;
    const float two_sg = 2.0f * sigma1;
    const float two_id = 2.0f / deltaF;

    // ---- 5. band-mapping coefficient registers ----
    // node(rr,cc) = (4*wrp+rr)*64 + 2*ln+cc ; idx = rr*2+cc
    const int row0 = wrp * 4, col0 = ln * 2;
    float cE[8], cS[8], cW0[4], cN0[2];
    int jbase[4];
    #pragma unroll
    for (int rr = 0; rr < 4; rr++) {
        int j = (row0 + rr) * 64 + col0 + 64;     // padded index of (rr, cc=0)
        jbase[rr] = j;
        cE[rr*2+0] = (float)S.cEd[j];
        cE[rr*2+1] = (float)S.cEd[j + 1];
        cS[rr*2+0] = (float)S.cSd[j];
        cS[rr*2+1] = (float)S.cSd[j + 1];
        cW0[rr]    = (float)S.cEd[j - 1];
    }
    cN0[0] = (float)S.cSd[jbase[0] - 64];
    cN0[1] = (float)S.cSd[jbase[0] - 63];

    double sb = 0.0;
    #pragma unroll
    for (int rr = 0; rr < 4; rr++) {
        double v0 = S.Bt[jbase[rr] - 64], v1 = S.Bt[jbase[rr] - 63];
        sb += v0 * v0 + v1 * v1;
    }
    const double rzb = bred_d(sb, S.red, tid);
    const double rz_target = rzb * 1e-16;

    // SpMV: t = A~ v ; ghosts from buffer `buf`
    auto spmv = [&](const float v[8], float t[8], int buf) {
        float2 gN = *(const float2*)&S.gBot[buf][wrp][col0];      // row row0-1
        float2 gS = *(const float2*)&S.gTop[buf][wrp + 2][col0];  // row row0+4
        #pragma unroll
        for (int rr = 0; rr < 4; rr++) {
            float vl = v[rr*2+0], vr = v[rr*2+1];
            float vW = __shfl_up_sync(0xffffffffu, vr, 1);
            float vE = __shfl_down_sync(0xffffffffu, vl, 1);
            float n0 = (rr == 0) ? gN.x : v[(rr-1)*2+0];
            float n1 = (rr == 0) ? gN.y : v[(rr-1)*2+1];
            float s0 = (rr == 3) ? gS.x : v[(rr+1)*2+0];
            float s1 = (rr == 3) ? gS.y : v[(rr+1)*2+1];
            float cn0 = (rr == 0) ? cN0[0] : cS[(rr-1)*2+0];
            float cn1 = (rr == 0) ? cN0[1] : cS[(rr-1)*2+1];
            t[rr*2+0] = vl + cW0[rr]   * vW + cE[rr*2+0] * vr
                           + cn0       * n0 + cS[rr*2+0] * s0;
            t[rr*2+1] = vr + cE[rr*2+0]* vl + cE[rr*2+1] * vE
                           + cn1       * n1 + cS[rr*2+1] * s1;
        }
    };
    auto stage = [&](const float v[8], int buf) {
        *(float2*)&S.gTop[buf][wrp + 1][col0] = make_float2(v[0], v[1]);
        *(float2*)&S.gBot[buf][wrp + 1][col0] = make_float2(v[6], v[7]);
    };

    // ---- 6. outer refinement passes ----
    for (int pass = 0; pass < 6; ++pass) {
        // fp64 residual (band mapping)
        double rdv[8];
        double rr64 = 0.0;
        #pragma unroll
        for (int rr = 0; rr < 4; rr++) {
            #pragma unroll
            for (int cc = 0; cc < 2; cc++) {
                int j = jbase[rr] + cc;
                double qd = S.Zs[j]
                          + S.cEd[j]      * S.Zs[j + 1]
                          + S.cEd[j - 1]  * S.Zs[j - 1]
                          + S.cSd[j]      * S.Zs[j + 64]
                          + S.cSd[j - 64] * S.Zs[j - 64];
                double rv = S.Bt[j - 64] - qd;
                rdv[rr*2+cc] = rv;
                rr64 += rv * rv;
            }
        }
        rr64 = bred_d(rr64, S.red, tid);
        if (!(rr64 > rz_target)) break;

        float r[8], p[8], q[8], dx[8];
        #pragma unroll
        for (int nn = 0; nn < 8; nn++) {
            r[nn] = (float)rdv[nn];
            p[nn] = 0.f; q[nn] = 0.f; dx[nn] = 0.f;
        }
        const float tolp = fmaxf((float)rz_target, (float)rr64 * 1e-11f);
        const int cap = (pass == 0) ? 160 : 80;
        float rho_old = 1.f, alpha_old = 1.f;
        float rrchk = (float)rr64;

        for (int it = 0; it < cap; ++it) {
            // --- z = P_D(A) r, w = A z  (Chebyshev, dot-free) ---
            float d_[8], z[8], rin[8], wacc[8];
            #pragma unroll
            for (int nn = 0; nn < 8; nn++) {
                d_[nn] = r[nn] * inv_th; z[nn] = d_[nn]; rin[nn] = r[nn];
            }
            stage(d_, 0);
            __syncthreads();
            float rhoC = rho0C;
            int buf = 0;
            #pragma unroll 1
            for (int k = 1; k <= CHEB_D; k++) {
                float t[8];
                spmv(d_, t, buf);
                float rhoN = __fdividef(1.f, two_sg - rhoC);
                float c1 = rhoN * rhoC, c2 = two_id * rhoN;
                #pragma unroll
                for (int nn = 0; nn < 8; nn++) {
                    rin[nn] -= t[nn];
                    wacc[nn] = (k == 1) ? t[nn] : wacc[nn] + t[nn];
                    d_[nn] = c1 * d_[nn] + c2 * rin[nn];
                    z[nn] += d_[nn];
                }
                rhoC = rhoN;
                buf ^= 1;
                stage(d_, buf);
                __syncthreads();
            }
            {
                float t[8];
                spmv(d_, t, buf);
                #pragma unroll
                for (int nn = 0; nn < 8; nn++) wacc[nn] += t[nn];
            }

            // --- fused dots: rho=(r,z), mu=(z,w), rr=(r,r) ---
            float pr = 0.f, pm = 0.f, prr = 0.f;
            #pragma unroll
            for (int nn = 0; nn < 8; nn++) {
                pr  += r[nn] * z[nn];
                pm  += z[nn] * wacc[nn];
                prr += r[nn] * r[nn];
            }
            float3 ds = bred3f(pr, pm, prr, S.red4, tid);
            float rho = ds.x, mu = ds.y, rrf = ds.z;

            if (!(rrf > tolp)) break;              // catches NaN too
            if ((it & 15) == 15) {                 // stagnation guard
                if (rrf > 0.9f * rrchk) break;
                rrchk = rrf;
            }
            if (!(rho > 0.f) || !(mu > 0.f)) break;

            float beta  = (it == 0) ? 0.f : __fdividef(rho, rho_old);
            float denom = mu - beta * __fdividef(rho, alpha_old);
            if (!(denom > 0.f)) break;
            float alpha = __fdividef(rho, denom);
            rho_old = rho; alpha_old = alpha;

            #pragma unroll
            for (int nn = 0; nn < 8; nn++) {
                p[nn] = z[nn] + beta * p[nn];
                q[nn] = wacc[nn] + beta * q[nn];
                dx[nn] += alpha * p[nn];
                r[nn]  -= alpha * q[nn];
            }
            // next iter's stage(d0 -> buf0) is WAR-safe: bred3f sync separates
        }

        __syncthreads();
        #pragma unroll
        for (int rr = 0; rr < 4; rr++) {
            S.Zs[jbase[rr] + 0] += (double)dx[rr*2+0];
            S.Zs[jbase[rr] + 1] += (double)dx[rr*2+1];
        }
        __syncthreads();
    }

    // ---- 7. outputs (band mapping) ----
    const double dtf = 3600.0;
    #pragma unroll
    for (int rr = 0; rr < 4; rr++) {
        #pragma unroll
        for (int cc = 0; cc < 2; cc++) {
            int i = jbase[rr] - 64 + cc;           // node index
            double x = S.Zs[i + 64] * S.isd[i];
            out[i] = (float)x;
            double P = (double)base[i] - x;
            const int* la = lan + 4 * i;
            double ssum = 0.0; int cnt = 0;
            #pragma unroll
            for (int k = 0; k < 4; k++) {
                int l = la[k];
                if (l >= 0) { ssum += (double)svel[l]; cnt++; }
            }
            double sliding = fabs(ssum / SEC_PER_A) / (double)(cnt > 0 ? cnt : 1);
            double nh = ((double)sheet[i] + dtf * sliding * HR_ / LR_)
                      / (1.0 + dtf * (sliding / LR_ + A_ * P * P * P));
            out[NN + i] = (float)nh;
        }
    }
}

extern "C" void kernel_launch(void* const* d_in, const int* in_sizes, int n_in,
                              void* d_out, int out_size)
{
    const float* base  = (const float*)d_in[0];
    const float* over  = (const float*)d_in[1];
    const float* melt  = (const float*)d_in[2];
    const float* sheet = (const float*)d_in[3];
    const float* pot   = (const float*)d_in[4];
    const float* svel  = (const float*)d_in[5];
    const float* llen  = (const float*)d_in[6];
    const int*   lan   = (const int*)d_in[9];
    const int*   infl  = (const int*)d_in[10];
    float* out = (float*)d_out;

    int smem = (int)sizeof(Smem);
    cudaFuncSetAttribute(sgd_kernel, cudaFuncAttributeMaxDynamicSharedMemorySize, smem);
    sgd_kernel<<<1, NT, smem>>>(base, over, melt, sheet, pot, svel, llen, lan, infl, out);
}